// round 13
// baseline (speedup 1.0000x reference)
#include <cuda_runtime.h>
#include <cuda_fp16.h>

#define N_NODES 100000
#define N_EDGES 1600000
#define F_IN 48
#define F_HID 16
#define F_OUT 16

// Scratch (device globals — no allocation allowed).
// Yh/Zh: fp16 per-node tables, interleaved per (node, quad):
//   uint4 at [node*4+q] = {a01, a23, b01, b23} for features q*4..q*4+3,
//   where a = x@W[0], b = x@W[1]. One LDG.128 per edge per quad.
__device__ uint4  g_Yh[N_NODES * 4];
__device__ uint4  g_Zh[N_NODES * 4];
__device__ float4 g_AGG[N_NODES * 4];  // fp32 accumulator (16 floats/node)
__device__ float4 g_r1[N_NODES * 4];   // x @ root1 + b1 (fp32)
__device__ float4 g_r2[N_NODES * 4];   // h @ root2 + b2 (fp32)
__device__ int    g_cnt[N_NODES];      // in-degree (same both layers)
__device__ int    g_is64;              // 1 if edge_index is int64

__device__ __forceinline__ void red_add_v4(float4* addr, float4 v)
{
    asm volatile("red.global.add.v4.f32 [%0], {%1, %2, %3, %4};"
                 :: "l"(addr), "f"(v.x), "f"(v.y), "f"(v.z), "f"(v.w)
                 : "memory");
}

__device__ __forceinline__ unsigned pack_h2(float lo, float hi)
{
    __half2 h = __floats2half2_rn(lo, hi);
    return *reinterpret_cast<unsigned*>(&h);
}
__device__ __forceinline__ float2 unpack_h2(unsigned u)
{
    __half2 h = *reinterpret_cast<__half2*>(&u);
    return __half22float2(h);
}

// ---------------------------------------------------------------------------
// Kernel 1: layer-1 per-node precompute (+ zero agg/cnt; + dtype detect in
// block 0). Block = 256 threads = 64 nodes x 4 feature-quads.
// ---------------------------------------------------------------------------
__global__ __launch_bounds__(256) void precompute1(
    const float* __restrict__ x,
    const float* __restrict__ W1,     // [2,48,16]
    const float* __restrict__ root1,  // [48,16]
    const float* __restrict__ b1,     // [16]
    const unsigned int* __restrict__ ei_words)
{
    __shared__ float sW0[F_IN * 16];
    __shared__ float sW1[F_IN * 16];
    __shared__ float sR [F_IN * 16];
    __shared__ float sx [64 * 49];       // pitch 49: conflict-free

    int tid = threadIdx.x;

    // dtype detect (block 0, warp 0): int64 node ids < 2^31 -> odd words zero
    if (blockIdx.x == 0 && tid < 32) {
        unsigned int v = 0;
        for (int i = tid; i < 2048; i += 32) v |= ei_words[2 * i + 1];
        unsigned int any = __any_sync(0xffffffffu, v != 0u);
        if (tid == 0) g_is64 = any ? 0 : 1;
    }

    for (int i = tid; i < F_IN * 16; i += 256) {
        sW0[i] = W1[i];
        sW1[i] = W1[F_IN * 16 + i];
        sR[i]  = root1[i];
    }
    int base = blockIdx.x * 64;
    for (int i = tid; i < 64 * F_IN; i += 256)
        sx[(i / F_IN) * 49 + (i % F_IN)] = x[base * F_IN + i];
    __syncthreads();

    int nl = tid >> 2;          // node within block (0..63)
    int q  = tid & 3;           // feature quad (0..3)
    int node = base + nl;

    float4 bq = ((const float4*)b1)[q];
    float4 a0 = {0, 0, 0, 0}, a1 = {0, 0, 0, 0}, ar = bq;
    #pragma unroll
    for (int c = 0; c < F_IN; c++) {
        float xv = sx[nl * 49 + c];
        float4 w0 = ((const float4*)sW0)[c * 4 + q];
        float4 w1 = ((const float4*)sW1)[c * 4 + q];
        float4 wr = ((const float4*)sR )[c * 4 + q];
        a0.x = fmaf(xv, w0.x, a0.x); a0.y = fmaf(xv, w0.y, a0.y);
        a0.z = fmaf(xv, w0.z, a0.z); a0.w = fmaf(xv, w0.w, a0.w);
        a1.x = fmaf(xv, w1.x, a1.x); a1.y = fmaf(xv, w1.y, a1.y);
        a1.z = fmaf(xv, w1.z, a1.z); a1.w = fmaf(xv, w1.w, a1.w);
        ar.x = fmaf(xv, wr.x, ar.x); ar.y = fmaf(xv, wr.y, ar.y);
        ar.z = fmaf(xv, wr.z, ar.z); ar.w = fmaf(xv, wr.w, ar.w);
    }
    g_Yh[node * 4 + q] = make_uint4(pack_h2(a0.x, a0.y), pack_h2(a0.z, a0.w),
                                    pack_h2(a1.x, a1.y), pack_h2(a1.z, a1.w));
    g_r1[node * 4 + q] = ar;
    g_AGG[node * 4 + q] = make_float4(0.f, 0.f, 0.f, 0.f);
    if (q == 0) g_cnt[node] = 0;
}

// ---------------------------------------------------------------------------
// Kernel 2/4: edge scatter. Each 4-lane quad handles FOUR consecutive edges.
// Vectorized index/attr loads (LDG.128), one LDG.128 gather + one RED.v4
// per edge per quad.
// ---------------------------------------------------------------------------
template <int LAYER>
__global__ __launch_bounds__(256) void edge_pass(
    const void* __restrict__ ei_raw,    // [2, N_EDGES] int32 or int64
    const float* __restrict__ ea)       // [N_EDGES] (u)
{
    int idx = blockIdx.x * 256 + threadIdx.x;   // < N_EDGES
    int g = idx >> 2;                           // edge group (4 edges)
    int q = idx & 3;                            // feature quad
    int e = 4 * g;

    int src[4], dst[4];
    if (g_is64) {
        const longlong2* es = (const longlong2*)((const char*)ei_raw + (size_t)e * 8);
        const longlong2* ed = (const longlong2*)((const char*)ei_raw + ((size_t)N_EDGES + e) * 8);
        longlong2 s0 = __ldg(&es[0]);
        longlong2 s1 = __ldg(&es[1]);
        longlong2 d0 = __ldg(&ed[0]);
        longlong2 d1 = __ldg(&ed[1]);
        src[0] = (int)s0.x; src[1] = (int)s0.y; src[2] = (int)s1.x; src[3] = (int)s1.y;
        dst[0] = (int)d0.x; dst[1] = (int)d0.y; dst[2] = (int)d1.x; dst[3] = (int)d1.y;
    } else {
        const int4* es = (const int4*)((const char*)ei_raw + (size_t)e * 4);
        const int4* ed = (const int4*)((const char*)ei_raw + ((size_t)N_EDGES + e) * 4);
        int4 s = __ldg(es);
        int4 d = __ldg(ed);
        src[0] = s.x; src[1] = s.y; src[2] = s.z; src[3] = s.w;
        dst[0] = d.x; dst[1] = d.y; dst[2] = d.z; dst[3] = d.w;
    }
    float4 uv = __ldg((const float4*)(ea + e));
    float u[4] = {uv.x, uv.y, uv.z, uv.w};

    const uint4* __restrict__ Y = LAYER ? g_Zh : g_Yh;

    // Issue all gathers first (max MLP), then math + REDs.
    uint4 r[4];
    bool ok[4];
    #pragma unroll
    for (int k = 0; k < 4; k++) {
        ok[k] = (unsigned)src[k] < N_NODES && (unsigned)dst[k] < N_NODES;
        int s = ok[k] ? src[k] : 0;
        r[k] = __ldg(&Y[s * 4 + q]);
    }

    #pragma unroll
    for (int k = 0; k < 4; k++) {
        if (!ok[k]) continue;
        float2 a01 = unpack_h2(r[k].x), a23 = unpack_h2(r[k].y);
        float2 b01 = unpack_h2(r[k].z), b23 = unpack_h2(r[k].w);
        float4 m;
        m.x = fmaf(u[k], b01.x - a01.x, a01.x);
        m.y = fmaf(u[k], b01.y - a01.y, a01.y);
        m.z = fmaf(u[k], b23.x - a23.x, a23.x);
        m.w = fmaf(u[k], b23.y - a23.y, a23.y);
        red_add_v4(&g_AGG[dst[k] * 4 + q], m);
        if (LAYER == 0 && q == 0) atomicAdd(&g_cnt[dst[k]], 1);
    }
}

// ---------------------------------------------------------------------------
// Kernel 3: finalize layer 1 (mean + root + bias + ELU) fused with the
// layer-2 per-node precompute; re-zeros agg for pass 2.
// Block = 256 threads = 64 nodes x 4 quads.
// ---------------------------------------------------------------------------
__global__ __launch_bounds__(256) void mid_fused(
    const float* __restrict__ W2,     // [2,16,16]
    const float* __restrict__ root2,  // [16,16]
    const float* __restrict__ b2)     // [16]
{
    __shared__ float sW0[16 * 16];
    __shared__ float sW1[16 * 16];
    __shared__ float sR [16 * 16];
    __shared__ float sh [64 * 17];    // pitch 17: conflict-free

    int tid = threadIdx.x;
    sW0[tid] = W2[tid];
    sW1[tid] = W2[256 + tid];
    sR [tid] = root2[tid];

    int base = blockIdx.x * 64;
    int nl = tid >> 2;
    int q  = tid & 3;
    int node = base + nl;

    float cnt = fmaxf((float)g_cnt[node], 1.f);
    float inv = 1.f / cnt;
    float4 agg = g_AGG[node * 4 + q];
    float4 r1  = g_r1[node * 4 + q];
    float4 v;
    v.x = agg.x * inv + r1.x;  v.y = agg.y * inv + r1.y;
    v.z = agg.z * inv + r1.z;  v.w = agg.w * inv + r1.w;
    v.x = (v.x > 0.f) ? v.x : expm1f(v.x);
    v.y = (v.y > 0.f) ? v.y : expm1f(v.y);
    v.z = (v.z > 0.f) ? v.z : expm1f(v.z);
    v.w = (v.w > 0.f) ? v.w : expm1f(v.w);
    sh[nl * 17 + q * 4 + 0] = v.x;
    sh[nl * 17 + q * 4 + 1] = v.y;
    sh[nl * 17 + q * 4 + 2] = v.z;
    sh[nl * 17 + q * 4 + 3] = v.w;
    g_AGG[node * 4 + q] = make_float4(0.f, 0.f, 0.f, 0.f);
    __syncthreads();

    float4 bq = ((const float4*)b2)[q];
    float4 a0 = {0, 0, 0, 0}, a1 = {0, 0, 0, 0}, ar = bq;
    #pragma unroll
    for (int c = 0; c < F_HID; c++) {
        float hv = sh[nl * 17 + c];
        float4 w0 = ((const float4*)sW0)[c * 4 + q];
        float4 w1 = ((const float4*)sW1)[c * 4 + q];
        float4 wr = ((const float4*)sR )[c * 4 + q];
        a0.x = fmaf(hv, w0.x, a0.x); a0.y = fmaf(hv, w0.y, a0.y);
        a0.z = fmaf(hv, w0.z, a0.z); a0.w = fmaf(hv, w0.w, a0.w);
        a1.x = fmaf(hv, w1.x, a1.x); a1.y = fmaf(hv, w1.y, a1.y);
        a1.z = fmaf(hv, w1.z, a1.z); a1.w = fmaf(hv, w1.w, a1.w);
        ar.x = fmaf(hv, wr.x, ar.x); ar.y = fmaf(hv, wr.y, ar.y);
        ar.z = fmaf(hv, wr.z, ar.z); ar.w = fmaf(hv, wr.w, ar.w);
    }
    g_Zh[node * 4 + q] = make_uint4(pack_h2(a0.x, a0.y), pack_h2(a0.z, a0.w),
                                    pack_h2(a1.x, a1.y), pack_h2(a1.z, a1.w));
    g_r2[node * 4 + q] = ar;
}

// ---------------------------------------------------------------------------
// Kernel 5: finalize layer 2 (mean + root + bias) + log_softmax over 16.
// Thread = (node, quad); reduction = local over 4 + shfl over 2 lanes.
// ---------------------------------------------------------------------------
__global__ __launch_bounds__(256) void finalize2(float4* __restrict__ out)
{
    int idx = blockIdx.x * 256 + threadIdx.x;   // < N_NODES*4
    int node = idx >> 2;

    float cnt = fmaxf((float)g_cnt[node], 1.f);
    float inv = 1.f / cnt;
    float4 agg = g_AGG[idx];
    float4 r2  = g_r2[idx];
    float4 v;
    v.x = agg.x * inv + r2.x;  v.y = agg.y * inv + r2.y;
    v.z = agg.z * inv + r2.z;  v.w = agg.w * inv + r2.w;

    float mx = fmaxf(fmaxf(v.x, v.y), fmaxf(v.z, v.w));
    mx = fmaxf(mx, __shfl_xor_sync(0xffffffffu, mx, 1));
    mx = fmaxf(mx, __shfl_xor_sync(0xffffffffu, mx, 2));

    float s = expf(v.x - mx) + expf(v.y - mx) + expf(v.z - mx) + expf(v.w - mx);
    s += __shfl_xor_sync(0xffffffffu, s, 1);
    s += __shfl_xor_sync(0xffffffffu, s, 2);

    float c = mx + logf(s);
    float4 r;
    r.x = v.x - c; r.y = v.y - c; r.z = v.z - c; r.w = v.w - c;
    out[idx] = r;
}

// ---------------------------------------------------------------------------
extern "C" void kernel_launch(void* const* d_in, const int* in_sizes, int n_in,
                              void* d_out, int out_size)
{
    const float* x     = (const float*)d_in[0];
    const float* ea    = (const float*)d_in[1];
    const void*  ei    = d_in[2];
    const float* W1    = (const float*)d_in[3];
    const float* root1 = (const float*)d_in[4];
    const float* b1    = (const float*)d_in[5];
    const float* W2    = (const float*)d_in[6];
    const float* root2 = (const float*)d_in[7];
    const float* b2    = (const float*)d_in[8];
    float4* out = (float4*)d_out;

    const int node_blocks = (N_NODES + 63) / 64;     // 1563
    const int nq_blocks   = (N_NODES * 4 + 255) / 256;
    const int edge_blocks = N_EDGES / 256;           // 6250

    precompute1<<<node_blocks, 256>>>(x, W1, root1, b1, (const unsigned int*)ei);
    edge_pass<0><<<edge_blocks, 256>>>(ei, ea);
    mid_fused<<<node_blocks, 256>>>(W2, root2, b2);
    edge_pass<1><<<edge_blocks, 256>>>(ei, ea);
    finalize2<<<nq_blocks, 256>>>(out);
}

// round 14
// speedup vs baseline: 1.1049x; 1.1049x over previous
#include <cuda_runtime.h>
#include <cuda_fp16.h>

#define N_NODES 100000
#define N_EDGES 1600000
#define F_IN 48
#define F_HID 16
#define F_OUT 16

// Scratch (device globals — no allocation allowed).
// Yh/Zh: fp16 per-node tables, interleaved per (node, quad):
//   uint4 at [node*4+q] = {a01, a23, b01, b23} for features q*4..q*4+3,
//   where a = x@W[0], b = x@W[1]. One LDG.128 per edge per quad.
__device__ uint4  g_Yh[N_NODES * 4];
__device__ uint4  g_Zh[N_NODES * 4];
__device__ float4 g_AGG[N_NODES * 4];  // fp32 accumulator (16 floats/node)
__device__ float4 g_r1[N_NODES * 4];   // x @ root1 + b1 (fp32)
__device__ float4 g_r2[N_NODES * 4];   // h @ root2 + b2 (fp32)
__device__ int    g_cnt[N_NODES];      // in-degree (same both layers)
__device__ int    g_is64;              // 1 if edge_index is int64

__device__ __forceinline__ void red_add_v4(float4* addr, float4 v)
{
    asm volatile("red.global.add.v4.f32 [%0], {%1, %2, %3, %4};"
                 :: "l"(addr), "f"(v.x), "f"(v.y), "f"(v.z), "f"(v.w)
                 : "memory");
}

__device__ __forceinline__ unsigned pack_h2(float lo, float hi)
{
    __half2 h = __floats2half2_rn(lo, hi);
    return *reinterpret_cast<unsigned*>(&h);
}
__device__ __forceinline__ float2 unpack_h2(unsigned u)
{
    __half2 h = *reinterpret_cast<__half2*>(&u);
    return __half22float2(h);
}

// Packed fp32x2 FMA (sm_103a FFMA2): d = a*b + c on two lanes, full fp32.
__device__ __forceinline__ unsigned long long fma_f32x2(
    unsigned long long a, unsigned long long b, unsigned long long c)
{
    unsigned long long d;
    asm("fma.rn.f32x2 %0, %1, %2, %3;" : "=l"(d) : "l"(a), "l"(b), "l"(c));
    return d;
}
__device__ __forceinline__ unsigned long long bcast_f32x2(float v)
{
    unsigned long long d;
    unsigned u = __float_as_uint(v);
    asm("mov.b64 %0, {%1, %1};" : "=l"(d) : "r"(u));
    return d;
}
__device__ __forceinline__ float2 unpack_f32x2(unsigned long long v)
{
    unsigned lo, hi;
    asm("mov.b64 {%0, %1}, %2;" : "=r"(lo), "=r"(hi) : "l"(v));
    return make_float2(__uint_as_float(lo), __uint_as_float(hi));
}

// ---------------------------------------------------------------------------
// Kernel 1: layer-1 per-node precompute (+ zero agg/cnt; + dtype detect in
// block 0). Block = 256 threads = 64 nodes x 4 feature-quads.
// Inner loop uses packed f32x2 FMA: 6 FFMA2 per k-step instead of 12 FFMA.
// ---------------------------------------------------------------------------
__global__ __launch_bounds__(256) void precompute1(
    const float* __restrict__ x,
    const float* __restrict__ W1,     // [2,48,16]
    const float* __restrict__ root1,  // [48,16]
    const float* __restrict__ b1,     // [16]
    const unsigned int* __restrict__ ei_words)
{
    __shared__ float sW0[F_IN * 16];
    __shared__ float sW1[F_IN * 16];
    __shared__ float sR [F_IN * 16];
    __shared__ float sx [64 * 49];       // pitch 49: conflict-free

    int tid = threadIdx.x;

    // dtype detect (block 0, warp 0): int64 node ids < 2^31 -> odd words zero
    if (blockIdx.x == 0 && tid < 32) {
        unsigned int v = 0;
        for (int i = tid; i < 2048; i += 32) v |= ei_words[2 * i + 1];
        unsigned int any = __any_sync(0xffffffffu, v != 0u);
        if (tid == 0) g_is64 = any ? 0 : 1;
    }

    for (int i = tid; i < F_IN * 16; i += 256) {
        sW0[i] = W1[i];
        sW1[i] = W1[F_IN * 16 + i];
        sR[i]  = root1[i];
    }
    int base = blockIdx.x * 64;
    for (int i = tid; i < 64 * F_IN; i += 256)
        sx[(i / F_IN) * 49 + (i % F_IN)] = x[base * F_IN + i];
    __syncthreads();

    int nl = tid >> 2;          // node within block (0..63)
    int q  = tid & 3;           // feature quad (0..3)
    int node = base + nl;

    typedef unsigned long long u64;
    float4 bq = ((const float4*)b1)[q];
    u64 a0l = 0, a0h = 0, a1l = 0, a1h = 0;   // packed fp32 pairs (0.0|0.0)
    u64 arl, arh;
    asm("mov.b64 %0, {%1, %2};" : "=l"(arl)
        : "r"(__float_as_uint(bq.x)), "r"(__float_as_uint(bq.y)));
    asm("mov.b64 %0, {%1, %2};" : "=l"(arh)
        : "r"(__float_as_uint(bq.z)), "r"(__float_as_uint(bq.w)));

    #pragma unroll
    for (int c = 0; c < F_IN; c++) {
        u64 xv2 = bcast_f32x2(sx[nl * 49 + c]);
        const u64* w0 = (const u64*)(sW0 + c * 16 + q * 4);
        const u64* w1 = (const u64*)(sW1 + c * 16 + q * 4);
        const u64* wr = (const u64*)(sR  + c * 16 + q * 4);
        a0l = fma_f32x2(xv2, w0[0], a0l);
        a0h = fma_f32x2(xv2, w0[1], a0h);
        a1l = fma_f32x2(xv2, w1[0], a1l);
        a1h = fma_f32x2(xv2, w1[1], a1h);
        arl = fma_f32x2(xv2, wr[0], arl);
        arh = fma_f32x2(xv2, wr[1], arh);
    }
    float2 a0xy = unpack_f32x2(a0l), a0zw = unpack_f32x2(a0h);
    float2 a1xy = unpack_f32x2(a1l), a1zw = unpack_f32x2(a1h);
    float2 arxy = unpack_f32x2(arl), arzw = unpack_f32x2(arh);

    g_Yh[node * 4 + q] = make_uint4(pack_h2(a0xy.x, a0xy.y), pack_h2(a0zw.x, a0zw.y),
                                    pack_h2(a1xy.x, a1xy.y), pack_h2(a1zw.x, a1zw.y));
    g_r1[node * 4 + q] = make_float4(arxy.x, arxy.y, arzw.x, arzw.y);
    g_AGG[node * 4 + q] = make_float4(0.f, 0.f, 0.f, 0.f);
    if (q == 0) g_cnt[node] = 0;
}

// ---------------------------------------------------------------------------
// Kernel 2/4: edge scatter (R12-proven form). Each 4-lane quad handles FOUR
// consecutive edges. One LDG.128 gather + one RED.v4 per edge per quad.
// ---------------------------------------------------------------------------
template <int LAYER>
__global__ __launch_bounds__(256) void edge_pass(
    const void* __restrict__ ei_raw,    // [2, N_EDGES] int32 or int64
    const float* __restrict__ ea)       // [N_EDGES] (u)
{
    int idx = blockIdx.x * 256 + threadIdx.x;   // < N_EDGES
    int g = idx >> 2;                           // edge group (4 edges)
    int q = idx & 3;                            // feature quad
    int e = 4 * g;

    int src[4], dst[4];
    if (g_is64) {
        const long long* ei = (const long long*)ei_raw;
        #pragma unroll
        for (int k = 0; k < 4; k++) {
            src[k] = (int)__ldg(&ei[e + k]);
            dst[k] = (int)__ldg(&ei[N_EDGES + e + k]);
        }
    } else {
        const int* ei = (const int*)ei_raw;
        #pragma unroll
        for (int k = 0; k < 4; k++) {
            src[k] = __ldg(&ei[e + k]);
            dst[k] = __ldg(&ei[N_EDGES + e + k]);
        }
    }
    float u[4];
    #pragma unroll
    for (int k = 0; k < 4; k++) u[k] = __ldg(&ea[e + k]);

    const uint4* __restrict__ Y = LAYER ? g_Zh : g_Yh;

    // Issue all gathers first (max MLP), then math + REDs.
    uint4 r[4];
    bool ok[4];
    #pragma unroll
    for (int k = 0; k < 4; k++) {
        ok[k] = (unsigned)src[k] < N_NODES && (unsigned)dst[k] < N_NODES;
        int s = ok[k] ? src[k] : 0;
        r[k] = __ldg(&Y[s * 4 + q]);
    }

    #pragma unroll
    for (int k = 0; k < 4; k++) {
        if (!ok[k]) continue;
        float2 a01 = unpack_h2(r[k].x), a23 = unpack_h2(r[k].y);
        float2 b01 = unpack_h2(r[k].z), b23 = unpack_h2(r[k].w);
        float4 m;
        m.x = fmaf(u[k], b01.x - a01.x, a01.x);
        m.y = fmaf(u[k], b01.y - a01.y, a01.y);
        m.z = fmaf(u[k], b23.x - a23.x, a23.x);
        m.w = fmaf(u[k], b23.y - a23.y, a23.y);
        red_add_v4(&g_AGG[dst[k] * 4 + q], m);
        if (LAYER == 0 && q == 0) atomicAdd(&g_cnt[dst[k]], 1);
    }
}

// ---------------------------------------------------------------------------
// Kernel 3: finalize layer 1 (mean + root + bias + ELU) fused with the
// layer-2 per-node precompute; re-zeros agg for pass 2. f32x2 inner loop.
// Block = 256 threads = 64 nodes x 4 quads.
// ---------------------------------------------------------------------------
__global__ __launch_bounds__(256) void mid_fused(
    const float* __restrict__ W2,     // [2,16,16]
    const float* __restrict__ root2,  // [16,16]
    const float* __restrict__ b2)     // [16]
{
    __shared__ float sW0[16 * 16];
    __shared__ float sW1[16 * 16];
    __shared__ float sR [16 * 16];
    __shared__ float sh [64 * 17];    // pitch 17: conflict-free

    int tid = threadIdx.x;
    sW0[tid] = W2[tid];
    sW1[tid] = W2[256 + tid];
    sR [tid] = root2[tid];

    int base = blockIdx.x * 64;
    int nl = tid >> 2;
    int q  = tid & 3;
    int node = base + nl;

    float cnt = fmaxf((float)g_cnt[node], 1.f);
    float inv = 1.f / cnt;
    float4 agg = g_AGG[node * 4 + q];
    float4 r1  = g_r1[node * 4 + q];
    float4 v;
    v.x = agg.x * inv + r1.x;  v.y = agg.y * inv + r1.y;
    v.z = agg.z * inv + r1.z;  v.w = agg.w * inv + r1.w;
    v.x = (v.x > 0.f) ? v.x : expm1f(v.x);
    v.y = (v.y > 0.f) ? v.y : expm1f(v.y);
    v.z = (v.z > 0.f) ? v.z : expm1f(v.z);
    v.w = (v.w > 0.f) ? v.w : expm1f(v.w);
    sh[nl * 17 + q * 4 + 0] = v.x;
    sh[nl * 17 + q * 4 + 1] = v.y;
    sh[nl * 17 + q * 4 + 2] = v.z;
    sh[nl * 17 + q * 4 + 3] = v.w;
    g_AGG[node * 4 + q] = make_float4(0.f, 0.f, 0.f, 0.f);
    __syncthreads();

    typedef unsigned long long u64;
    float4 bq = ((const float4*)b2)[q];
    u64 a0l = 0, a0h = 0, a1l = 0, a1h = 0;
    u64 arl, arh;
    asm("mov.b64 %0, {%1, %2};" : "=l"(arl)
        : "r"(__float_as_uint(bq.x)), "r"(__float_as_uint(bq.y)));
    asm("mov.b64 %0, {%1, %2};" : "=l"(arh)
        : "r"(__float_as_uint(bq.z)), "r"(__float_as_uint(bq.w)));

    #pragma unroll
    for (int c = 0; c < F_HID; c++) {
        u64 hv2 = bcast_f32x2(sh[nl * 17 + c]);
        const u64* w0 = (const u64*)(sW0 + c * 16 + q * 4);
        const u64* w1 = (const u64*)(sW1 + c * 16 + q * 4);
        const u64* wr = (const u64*)(sR  + c * 16 + q * 4);
        a0l = fma_f32x2(hv2, w0[0], a0l);
        a0h = fma_f32x2(hv2, w0[1], a0h);
        a1l = fma_f32x2(hv2, w1[0], a1l);
        a1h = fma_f32x2(hv2, w1[1], a1h);
        arl = fma_f32x2(hv2, wr[0], arl);
        arh = fma_f32x2(hv2, wr[1], arh);
    }
    float2 a0xy = unpack_f32x2(a0l), a0zw = unpack_f32x2(a0h);
    float2 a1xy = unpack_f32x2(a1l), a1zw = unpack_f32x2(a1h);
    float2 arxy = unpack_f32x2(arl), arzw = unpack_f32x2(arh);

    g_Zh[node * 4 + q] = make_uint4(pack_h2(a0xy.x, a0xy.y), pack_h2(a0zw.x, a0zw.y),
                                    pack_h2(a1xy.x, a1xy.y), pack_h2(a1zw.x, a1zw.y));
    g_r2[node * 4 + q] = make_float4(arxy.x, arxy.y, arzw.x, arzw.y);
}

// ---------------------------------------------------------------------------
// Kernel 5: finalize layer 2 (mean + root + bias) + log_softmax over 16.
// Thread = (node, quad); reduction = local over 4 + shfl over 2 lanes.
// ---------------------------------------------------------------------------
__global__ __launch_bounds__(256) void finalize2(float4* __restrict__ out)
{
    int idx = blockIdx.x * 256 + threadIdx.x;   // < N_NODES*4
    int node = idx >> 2;

    float cnt = fmaxf((float)g_cnt[node], 1.f);
    float inv = 1.f / cnt;
    float4 agg = g_AGG[idx];
    float4 r2  = g_r2[idx];
    float4 v;
    v.x = agg.x * inv + r2.x;  v.y = agg.y * inv + r2.y;
    v.z = agg.z * inv + r2.z;  v.w = agg.w * inv + r2.w;

    float mx = fmaxf(fmaxf(v.x, v.y), fmaxf(v.z, v.w));
    mx = fmaxf(mx, __shfl_xor_sync(0xffffffffu, mx, 1));
    mx = fmaxf(mx, __shfl_xor_sync(0xffffffffu, mx, 2));

    float s = expf(v.x - mx) + expf(v.y - mx) + expf(v.z - mx) + expf(v.w - mx);
    s += __shfl_xor_sync(0xffffffffu, s, 1);
    s += __shfl_xor_sync(0xffffffffu, s, 2);

    float c = mx + logf(s);
    float4 r;
    r.x = v.x - c; r.y = v.y - c; r.z = v.z - c; r.w = v.w - c;
    out[idx] = r;
}

// ---------------------------------------------------------------------------
extern "C" void kernel_launch(void* const* d_in, const int* in_sizes, int n_in,
                              void* d_out, int out_size)
{
    const float* x     = (const float*)d_in[0];
    const float* ea    = (const float*)d_in[1];
    const void*  ei    = d_in[2];
    const float* W1    = (const float*)d_in[3];
    const float* root1 = (const float*)d_in[4];
    const float* b1    = (const float*)d_in[5];
    const float* W2    = (const float*)d_in[6];
    const float* root2 = (const float*)d_in[7];
    const float* b2    = (const float*)d_in[8];
    float4* out = (float4*)d_out;

    const int node_blocks = (N_NODES + 63) / 64;     // 1563
    const int nq_blocks   = (N_NODES * 4 + 255) / 256;
    const int edge_blocks = N_EDGES / 256;           // 6250

    precompute1<<<node_blocks, 256>>>(x, W1, root1, b1, (const unsigned int*)ei);
    edge_pass<0><<<edge_blocks, 256>>>(ei, ea);
    mid_fused<<<node_blocks, 256>>>(W2, root2, b2);
    edge_pass<1><<<edge_blocks, 256>>>(ei, ea);
    finalize2<<<nq_blocks, 256>>>(out);
}

// round 15
// speedup vs baseline: 1.2005x; 1.0865x over previous
#include <cuda_runtime.h>
#include <cuda_fp16.h>

#define N_NODES 100000
#define N_EDGES 1600000
#define F_IN 48
#define F_HID 16
#define F_OUT 16

// Scratch (device globals — no allocation allowed).
// Yh/Zh: fp16 per-node tables, interleaved per (node, quad):
//   uint4 at [node*4+q] = {a01, a23, b01, b23} for features q*4..q*4+3,
//   where a = x@W[0], b = x@W[1]. One LDG.128 per edge per quad.
__device__ uint4  g_Yh[N_NODES * 4];
__device__ uint4  g_Zh[N_NODES * 4];
__device__ float4 g_AGG[N_NODES * 4];  // fp32 accumulator (16 floats/node)
__device__ float4 g_r1[N_NODES * 4];   // x @ root1 + b1 (fp32)
__device__ float4 g_r2[N_NODES * 4];   // h @ root2 + b2 (fp32)
__device__ int    g_cnt[N_NODES];      // in-degree (same both layers)
__device__ int    g_is64;              // 1 if edge_index is int64

__device__ __forceinline__ void red_add_v4(float4* addr, float4 v)
{
    asm volatile("red.global.add.v4.f32 [%0], {%1, %2, %3, %4};"
                 :: "l"(addr), "f"(v.x), "f"(v.y), "f"(v.z), "f"(v.w)
                 : "memory");
}

__device__ __forceinline__ unsigned pack_h2(float lo, float hi)
{
    __half2 h = __floats2half2_rn(lo, hi);
    return *reinterpret_cast<unsigned*>(&h);
}
__device__ __forceinline__ float2 unpack_h2(unsigned u)
{
    __half2 h = *reinterpret_cast<__half2*>(&u);
    return __half22float2(h);
}

// Packed fp32x2 FMA (sm_103a FFMA2): d = a*b + c on two lanes, full fp32.
__device__ __forceinline__ unsigned long long fma_f32x2(
    unsigned long long a, unsigned long long b, unsigned long long c)
{
    unsigned long long d;
    asm("fma.rn.f32x2 %0, %1, %2, %3;" : "=l"(d) : "l"(a), "l"(b), "l"(c));
    return d;
}
__device__ __forceinline__ unsigned long long bcast_f32x2(float v)
{
    unsigned long long d;
    unsigned u = __float_as_uint(v);
    asm("mov.b64 %0, {%1, %1};" : "=l"(d) : "r"(u));
    return d;
}
__device__ __forceinline__ unsigned long long pack_f32x2(float lo, float hi)
{
    unsigned long long d;
    asm("mov.b64 %0, {%1, %2};" : "=l"(d)
        : "r"(__float_as_uint(lo)), "r"(__float_as_uint(hi)));
    return d;
}
__device__ __forceinline__ float2 unpack_f32x2(unsigned long long v)
{
    unsigned lo, hi;
    asm("mov.b64 {%0, %1}, %2;" : "=r"(lo), "=r"(hi) : "l"(v));
    return make_float2(__uint_as_float(lo), __uint_as_float(hi));
}

// ---------------------------------------------------------------------------
// Kernel 1: layer-1 per-node precompute (+ zero agg/cnt; + dtype detect in
// block 0). Block = 256 threads = 256 nodes (4 nodes/thread, stride 64)
// x 4 feature-quads. Weight LDS amortized over 4 nodes via register blocking.
// ---------------------------------------------------------------------------
__global__ __launch_bounds__(256) void precompute1(
    const float* __restrict__ x,
    const float* __restrict__ W1,     // [2,48,16]
    const float* __restrict__ root1,  // [48,16]
    const float* __restrict__ b1,     // [16]
    const unsigned int* __restrict__ ei_words)
{
    __shared__ float sW0[F_IN * 16];
    __shared__ float sW1[F_IN * 16];
    __shared__ float sR [F_IN * 16];
    __shared__ float sx [256 * 49];      // pitch 49: conflict-free

    int tid = threadIdx.x;

    // dtype detect (block 0, warp 0): int64 node ids < 2^31 -> odd words zero
    if (blockIdx.x == 0 && tid < 32) {
        unsigned int v = 0;
        for (int i = tid; i < 2048; i += 32) v |= ei_words[2 * i + 1];
        unsigned int any = __any_sync(0xffffffffu, v != 0u);
        if (tid == 0) g_is64 = any ? 0 : 1;
    }

    for (int i = tid; i < F_IN * 16; i += 256) {
        sW0[i] = W1[i];
        sW1[i] = W1[F_IN * 16 + i];
        sR[i]  = root1[i];
    }
    int base = blockIdx.x * 256;
    for (int i = tid; i < 256 * F_IN; i += 256) {
        int nloc = i / F_IN;
        if (base + nloc < N_NODES)
            sx[nloc * 49 + (i % F_IN)] = x[(base + nloc) * F_IN + (i % F_IN)];
    }
    __syncthreads();

    typedef unsigned long long u64;
    int q  = tid & 3;           // feature quad (0..3)
    int ng = tid >> 2;          // node group (0..63); nodes = ng + j*64

    float4 bq = ((const float4*)b1)[q];
    u64 a0l[4], a0h[4], a1l[4], a1h[4], arl[4], arh[4];
    #pragma unroll
    for (int j = 0; j < 4; j++) {
        a0l[j] = a0h[j] = a1l[j] = a1h[j] = 0;
        arl[j] = pack_f32x2(bq.x, bq.y);
        arh[j] = pack_f32x2(bq.z, bq.w);
    }

    #pragma unroll 4
    for (int c = 0; c < F_IN; c++) {
        const u64* w0 = (const u64*)(sW0 + c * 16 + q * 4);
        const u64* w1 = (const u64*)(sW1 + c * 16 + q * 4);
        const u64* wr = (const u64*)(sR  + c * 16 + q * 4);
        u64 w0l = w0[0], w0h = w0[1];
        u64 w1l = w1[0], w1h = w1[1];
        u64 wrl = wr[0], wrh = wr[1];
        #pragma unroll
        for (int j = 0; j < 4; j++) {
            u64 xv2 = bcast_f32x2(sx[(ng + j * 64) * 49 + c]);
            a0l[j] = fma_f32x2(xv2, w0l, a0l[j]);
            a0h[j] = fma_f32x2(xv2, w0h, a0h[j]);
            a1l[j] = fma_f32x2(xv2, w1l, a1l[j]);
            a1h[j] = fma_f32x2(xv2, w1h, a1h[j]);
            arl[j] = fma_f32x2(xv2, wrl, arl[j]);
            arh[j] = fma_f32x2(xv2, wrh, arh[j]);
        }
    }

    #pragma unroll
    for (int j = 0; j < 4; j++) {
        int node = base + ng + j * 64;
        if (node >= N_NODES) break;
        float2 a0xy = unpack_f32x2(a0l[j]), a0zw = unpack_f32x2(a0h[j]);
        float2 a1xy = unpack_f32x2(a1l[j]), a1zw = unpack_f32x2(a1h[j]);
        float2 arxy = unpack_f32x2(arl[j]), arzw = unpack_f32x2(arh[j]);
        g_Yh[node * 4 + q] = make_uint4(pack_h2(a0xy.x, a0xy.y), pack_h2(a0zw.x, a0zw.y),
                                        pack_h2(a1xy.x, a1xy.y), pack_h2(a1zw.x, a1zw.y));
        g_r1[node * 4 + q] = make_float4(arxy.x, arxy.y, arzw.x, arzw.y);
        g_AGG[node * 4 + q] = make_float4(0.f, 0.f, 0.f, 0.f);
        if (q == 0) g_cnt[node] = 0;
    }
}

// ---------------------------------------------------------------------------
// Kernel 2/4: edge scatter (R12-proven form). Each 4-lane quad handles FOUR
// consecutive edges. One LDG.128 gather + one RED.v4 per edge per quad.
// ---------------------------------------------------------------------------
template <int LAYER>
__global__ __launch_bounds__(256) void edge_pass(
    const void* __restrict__ ei_raw,    // [2, N_EDGES] int32 or int64
    const float* __restrict__ ea)       // [N_EDGES] (u)
{
    int idx = blockIdx.x * 256 + threadIdx.x;   // < N_EDGES
    int g = idx >> 2;                           // edge group (4 edges)
    int q = idx & 3;                            // feature quad
    int e = 4 * g;

    int src[4], dst[4];
    if (g_is64) {
        const long long* ei = (const long long*)ei_raw;
        #pragma unroll
        for (int k = 0; k < 4; k++) {
            src[k] = (int)__ldg(&ei[e + k]);
            dst[k] = (int)__ldg(&ei[N_EDGES + e + k]);
        }
    } else {
        const int* ei = (const int*)ei_raw;
        #pragma unroll
        for (int k = 0; k < 4; k++) {
            src[k] = __ldg(&ei[e + k]);
            dst[k] = __ldg(&ei[N_EDGES + e + k]);
        }
    }
    float u[4];
    #pragma unroll
    for (int k = 0; k < 4; k++) u[k] = __ldg(&ea[e + k]);

    const uint4* __restrict__ Y = LAYER ? g_Zh : g_Yh;

    // Issue all gathers first (max MLP), then math + REDs.
    uint4 r[4];
    bool ok[4];
    #pragma unroll
    for (int k = 0; k < 4; k++) {
        ok[k] = (unsigned)src[k] < N_NODES && (unsigned)dst[k] < N_NODES;
        int s = ok[k] ? src[k] : 0;
        r[k] = __ldg(&Y[s * 4 + q]);
    }

    #pragma unroll
    for (int k = 0; k < 4; k++) {
        if (!ok[k]) continue;
        float2 a01 = unpack_h2(r[k].x), a23 = unpack_h2(r[k].y);
        float2 b01 = unpack_h2(r[k].z), b23 = unpack_h2(r[k].w);
        float4 m;
        m.x = fmaf(u[k], b01.x - a01.x, a01.x);
        m.y = fmaf(u[k], b01.y - a01.y, a01.y);
        m.z = fmaf(u[k], b23.x - a23.x, a23.x);
        m.w = fmaf(u[k], b23.y - a23.y, a23.y);
        red_add_v4(&g_AGG[dst[k] * 4 + q], m);
        if (LAYER == 0 && q == 0) atomicAdd(&g_cnt[dst[k]], 1);
    }
}

// ---------------------------------------------------------------------------
// Kernel 3: finalize layer 1 (mean + root + bias + ELU) fused with the
// layer-2 per-node precompute; re-zeros agg for pass 2. f32x2 inner loop.
// Block = 256 threads = 64 nodes x 4 quads.
// ---------------------------------------------------------------------------
__global__ __launch_bounds__(256) void mid_fused(
    const float* __restrict__ W2,     // [2,16,16]
    const float* __restrict__ root2,  // [16,16]
    const float* __restrict__ b2)     // [16]
{
    __shared__ float sW0[16 * 16];
    __shared__ float sW1[16 * 16];
    __shared__ float sR [16 * 16];
    __shared__ float sh [64 * 17];    // pitch 17: conflict-free

    int tid = threadIdx.x;
    sW0[tid] = W2[tid];
    sW1[tid] = W2[256 + tid];
    sR [tid] = root2[tid];

    int base = blockIdx.x * 64;
    int nl = tid >> 2;
    int q  = tid & 3;
    int node = base + nl;

    float cnt = fmaxf((float)g_cnt[node], 1.f);
    float inv = 1.f / cnt;
    float4 agg = g_AGG[node * 4 + q];
    float4 r1  = g_r1[node * 4 + q];
    float4 v;
    v.x = agg.x * inv + r1.x;  v.y = agg.y * inv + r1.y;
    v.z = agg.z * inv + r1.z;  v.w = agg.w * inv + r1.w;
    v.x = (v.x > 0.f) ? v.x : expm1f(v.x);
    v.y = (v.y > 0.f) ? v.y : expm1f(v.y);
    v.z = (v.z > 0.f) ? v.z : expm1f(v.z);
    v.w = (v.w > 0.f) ? v.w : expm1f(v.w);
    sh[nl * 17 + q * 4 + 0] = v.x;
    sh[nl * 17 + q * 4 + 1] = v.y;
    sh[nl * 17 + q * 4 + 2] = v.z;
    sh[nl * 17 + q * 4 + 3] = v.w;
    g_AGG[node * 4 + q] = make_float4(0.f, 0.f, 0.f, 0.f);
    __syncthreads();

    typedef unsigned long long u64;
    float4 bq = ((const float4*)b2)[q];
    u64 a0l = 0, a0h = 0, a1l = 0, a1h = 0;
    u64 arl = pack_f32x2(bq.x, bq.y);
    u64 arh = pack_f32x2(bq.z, bq.w);

    #pragma unroll
    for (int c = 0; c < F_HID; c++) {
        u64 hv2 = bcast_f32x2(sh[nl * 17 + c]);
        const u64* w0 = (const u64*)(sW0 + c * 16 + q * 4);
        const u64* w1 = (const u64*)(sW1 + c * 16 + q * 4);
        const u64* wr = (const u64*)(sR  + c * 16 + q * 4);
        a0l = fma_f32x2(hv2, w0[0], a0l);
        a0h = fma_f32x2(hv2, w0[1], a0h);
        a1l = fma_f32x2(hv2, w1[0], a1l);
        a1h = fma_f32x2(hv2, w1[1], a1h);
        arl = fma_f32x2(hv2, wr[0], arl);
        arh = fma_f32x2(hv2, wr[1], arh);
    }
    float2 a0xy = unpack_f32x2(a0l), a0zw = unpack_f32x2(a0h);
    float2 a1xy = unpack_f32x2(a1l), a1zw = unpack_f32x2(a1h);
    float2 arxy = unpack_f32x2(arl), arzw = unpack_f32x2(arh);

    g_Zh[node * 4 + q] = make_uint4(pack_h2(a0xy.x, a0xy.y), pack_h2(a0zw.x, a0zw.y),
                                    pack_h2(a1xy.x, a1xy.y), pack_h2(a1zw.x, a1zw.y));
    g_r2[node * 4 + q] = make_float4(arxy.x, arxy.y, arzw.x, arzw.y);
}

// ---------------------------------------------------------------------------
// Kernel 5: finalize layer 2 (mean + root + bias) + log_softmax over 16.
// Thread = (node, quad); reduction = local over 4 + shfl over 2 lanes.
// ---------------------------------------------------------------------------
__global__ __launch_bounds__(256) void finalize2(float4* __restrict__ out)
{
    int idx = blockIdx.x * 256 + threadIdx.x;   // < N_NODES*4
    int node = idx >> 2;

    float cnt = fmaxf((float)g_cnt[node], 1.f);
    float inv = 1.f / cnt;
    float4 agg = g_AGG[idx];
    float4 r2  = g_r2[idx];
    float4 v;
    v.x = agg.x * inv + r2.x;  v.y = agg.y * inv + r2.y;
    v.z = agg.z * inv + r2.z;  v.w = agg.w * inv + r2.w;

    float mx = fmaxf(fmaxf(v.x, v.y), fmaxf(v.z, v.w));
    mx = fmaxf(mx, __shfl_xor_sync(0xffffffffu, mx, 1));
    mx = fmaxf(mx, __shfl_xor_sync(0xffffffffu, mx, 2));

    float s = expf(v.x - mx) + expf(v.y - mx) + expf(v.z - mx) + expf(v.w - mx);
    s += __shfl_xor_sync(0xffffffffu, s, 1);
    s += __shfl_xor_sync(0xffffffffu, s, 2);

    float c = mx + logf(s);
    float4 r;
    r.x = v.x - c; r.y = v.y - c; r.z = v.z - c; r.w = v.w - c;
    out[idx] = r;
}

// ---------------------------------------------------------------------------
extern "C" void kernel_launch(void* const* d_in, const int* in_sizes, int n_in,
                              void* d_out, int out_size)
{
    const float* x     = (const float*)d_in[0];
    const float* ea    = (const float*)d_in[1];
    const void*  ei    = d_in[2];
    const float* W1    = (const float*)d_in[3];
    const float* root1 = (const float*)d_in[4];
    const float* b1    = (const float*)d_in[5];
    const float* W2    = (const float*)d_in[6];
    const float* root2 = (const float*)d_in[7];
    const float* b2    = (const float*)d_in[8];
    float4* out = (float4*)d_out;

    const int pre_blocks  = (N_NODES + 255) / 256;   // 391
    const int node_blocks = (N_NODES + 63) / 64;     // 1563
    const int nq_blocks   = (N_NODES * 4 + 255) / 256;
    const int edge_blocks = N_EDGES / 256;           // 6250

    precompute1<<<pre_blocks, 256>>>(x, W1, root1, b1, (const unsigned int*)ei);
    edge_pass<0><<<edge_blocks, 256>>>(ei, ea);
    mid_fused<<<node_blocks, 256>>>(W2, root2, b2);
    edge_pass<1><<<edge_blocks, 256>>>(ei, ea);
    finalize2<<<nq_blocks, 256>>>(out);
}